// round 6
// baseline (speedup 1.0000x reference)
#include <cuda_runtime.h>
#include <stdint.h>

// Hadamard on qubit TARGET=5 of a 24-qubit real fp32 statevector, batch 2.
// Layout (row-major): idx = b*2^24 + l*2^19 + s*2^18 + r  (L=32, R=2^18).
// Pair partner is at element-stride 2^18 (bit 18). In float4 units the
// partner stride is 2^16, and the low 16 bits of the float4 index are the
// r-coordinate, so both streams stay perfectly coalesced.
//
// Total float4s: 2*2^24/4 = 2^23.  Pairs of float4s: 2^22.

__global__ void __launch_bounds__(256) hadamard_q5_kernel(
    const float4* __restrict__ in, float4* __restrict__ out)
{
    const unsigned t = blockIdx.x * blockDim.x + threadIdx.x;  // pair index, [0, 2^22)
    const float s = 0.70710678118654752440f;

    // i0: float4 index with "partner bit" (bit 16 in float4 units) = 0
    const unsigned i0 = ((t >> 16) << 17) + (t & 0xFFFFu);
    const unsigned i1 = i0 + (1u << 16);

    const float4 a = in[i0];
    const float4 b = in[i1];

    float4 u, v;
    u.x = (a.x + b.x) * s;  v.x = (a.x - b.x) * s;
    u.y = (a.y + b.y) * s;  v.y = (a.y - b.y) * s;
    u.z = (a.z + b.z) * s;  v.z = (a.z - b.z) * s;
    u.w = (a.w + b.w) * s;  v.w = (a.w - b.w) * s;

    out[i0] = u;
    out[i1] = v;
}

extern "C" void kernel_launch(void* const* d_in, const int* in_sizes, int n_in,
                              void* d_out, int out_size)
{
    const float4* in  = (const float4*)d_in[0];
    float4*       out = (float4*)d_out;

    // 2^22 pairs of float4s, 256 threads/block -> 16384 blocks
    const unsigned n_pairs = 1u << 22;
    const unsigned threads = 256;
    const unsigned blocks  = n_pairs / threads;  // 16384

    hadamard_q5_kernel<<<blocks, threads>>>(in, out);
}

// round 8
// speedup vs baseline: 1.0224x; 1.0224x over previous
#include <cuda_runtime.h>
#include <stdint.h>

// Hadamard on qubit TARGET=5 of a 24-qubit real fp32 statevector, batch 2.
// Pair partner at element-stride 2^18 (bit 18) => float4-stride 2^16.
// Total float4s: 2^23. Pairs: 2^22. Each thread handles TWO pairs
// (4 independent LDG.128 front-batched for MLP), split across the grid so
// every stream stays perfectly coalesced. Streaming cache hints (.cs) since
// no byte is ever reused.

__global__ void __launch_bounds__(256) hadamard_q5_kernel(
    const float4* __restrict__ in, float4* __restrict__ out)
{
    const unsigned t = blockIdx.x * blockDim.x + threadIdx.x;  // [0, 2^21)
    const float s = 0.70710678118654752440f;

    // Two pair indices, far apart so coalescing is preserved per-stream.
    const unsigned p0 = t;
    const unsigned p1 = t + (1u << 21);

    const unsigned a0 = ((p0 >> 16) << 17) + (p0 & 0xFFFFu);
    const unsigned a1 = a0 + (1u << 16);
    const unsigned b0 = ((p1 >> 16) << 17) + (p1 & 0xFFFFu);
    const unsigned b1 = b0 + (1u << 16);

    // Front-batch all four loads (MLP=4), evict-first.
    const float4 xa = __ldcs(in + a0);
    const float4 xb = __ldcs(in + a1);
    const float4 ya = __ldcs(in + b0);
    const float4 yb = __ldcs(in + b1);

    float4 u, v;
    u.x = (xa.x + xb.x) * s;  v.x = (xa.x - xb.x) * s;
    u.y = (xa.y + xb.y) * s;  v.y = (xa.y - xb.y) * s;
    u.z = (xa.z + xb.z) * s;  v.z = (xa.z - xb.z) * s;
    u.w = (xa.w + xb.w) * s;  v.w = (xa.w - xb.w) * s;
    __stcs(out + a0, u);
    __stcs(out + a1, v);

    float4 p, q;
    p.x = (ya.x + yb.x) * s;  q.x = (ya.x - yb.x) * s;
    p.y = (ya.y + yb.y) * s;  q.y = (ya.y - yb.y) * s;
    p.z = (ya.z + yb.z) * s;  q.z = (ya.z - yb.z) * s;
    p.w = (ya.w + yb.w) * s;  q.w = (ya.w - yb.w) * s;
    __stcs(out + b0, p);
    __stcs(out + b1, q);
}

extern "C" void kernel_launch(void* const* d_in, const int* in_sizes, int n_in,
                              void* d_out, int out_size)
{
    const float4* in  = (const float4*)d_in[0];
    float4*       out = (float4*)d_out;

    // 2^22 pairs, 2 pairs/thread -> 2^21 threads -> 8192 blocks of 256
    const unsigned threads = 256;
    const unsigned blocks  = (1u << 21) / threads;  // 8192

    hadamard_q5_kernel<<<blocks, threads>>>(in, out);
}

// round 9
// speedup vs baseline: 1.0382x; 1.0154x over previous
#include <cuda_runtime.h>
#include <stdint.h>

// Hadamard on qubit TARGET=5 of a 24-qubit real fp32 statevector, batch 2.
// Pair partner at element-stride 2^18 => float4-stride 2^16.
// 2^23 float4s total, 2^22 pairs. Each thread handles FOUR pairs
// (8 independent LDG.128 front-batched, MLP=8), grid-split into four
// streams so every access stays perfectly coalesced. Streaming hints (.cs)
// since no byte is reused.

__global__ void __launch_bounds__(256) hadamard_q5_kernel(
    const float4* __restrict__ in, float4* __restrict__ out)
{
    const unsigned t = blockIdx.x * blockDim.x + threadIdx.x;  // [0, 2^20)
    const float s = 0.70710678118654752440f;

    // Four pair indices in four widely separated streams.
    const unsigned p0 = t;
    const unsigned p1 = t + (1u << 20);
    const unsigned p2 = t + (2u << 20);
    const unsigned p3 = t + (3u << 20);

    const unsigned a0 = ((p0 >> 16) << 17) + (p0 & 0xFFFFu);
    const unsigned b0 = ((p1 >> 16) << 17) + (p1 & 0xFFFFu);
    const unsigned c0 = ((p2 >> 16) << 17) + (p2 & 0xFFFFu);
    const unsigned d0 = ((p3 >> 16) << 17) + (p3 & 0xFFFFu);
    const unsigned STEP = 1u << 16;

    // Front-batch all eight loads (MLP=8), evict-first.
    const float4 xa = __ldcs(in + a0);
    const float4 xb = __ldcs(in + a0 + STEP);
    const float4 ya = __ldcs(in + b0);
    const float4 yb = __ldcs(in + b0 + STEP);
    const float4 za = __ldcs(in + c0);
    const float4 zb = __ldcs(in + c0 + STEP);
    const float4 wa = __ldcs(in + d0);
    const float4 wb = __ldcs(in + d0 + STEP);

    float4 u, v;
    u.x = (xa.x + xb.x) * s;  v.x = (xa.x - xb.x) * s;
    u.y = (xa.y + xb.y) * s;  v.y = (xa.y - xb.y) * s;
    u.z = (xa.z + xb.z) * s;  v.z = (xa.z - xb.z) * s;
    u.w = (xa.w + xb.w) * s;  v.w = (xa.w - xb.w) * s;
    __stcs(out + a0, u);
    __stcs(out + a0 + STEP, v);

    u.x = (ya.x + yb.x) * s;  v.x = (ya.x - yb.x) * s;
    u.y = (ya.y + yb.y) * s;  v.y = (ya.y - yb.y) * s;
    u.z = (ya.z + yb.z) * s;  v.z = (ya.z - yb.z) * s;
    u.w = (ya.w + yb.w) * s;  v.w = (ya.w - yb.w) * s;
    __stcs(out + b0, u);
    __stcs(out + b0 + STEP, v);

    u.x = (za.x + zb.x) * s;  v.x = (za.x - zb.x) * s;
    u.y = (za.y + zb.y) * s;  v.y = (za.y - zb.y) * s;
    u.z = (za.z + zb.z) * s;  v.z = (za.z - zb.z) * s;
    u.w = (za.w + zb.w) * s;  v.w = (za.w - zb.w) * s;
    __stcs(out + c0, u);
    __stcs(out + c0 + STEP, v);

    u.x = (wa.x + wb.x) * s;  v.x = (wa.x - wb.x) * s;
    u.y = (wa.y + wb.y) * s;  v.y = (wa.y - wb.y) * s;
    u.z = (wa.z + wb.z) * s;  v.z = (wa.z - wb.z) * s;
    u.w = (wa.w + wb.w) * s;  v.w = (wa.w - wb.w) * s;
    __stcs(out + d0, u);
    __stcs(out + d0 + STEP, v);
}

extern "C" void kernel_launch(void* const* d_in, const int* in_sizes, int n_in,
                              void* d_out, int out_size)
{
    const float4* in  = (const float4*)d_in[0];
    float4*       out = (float4*)d_out;

    // 2^22 pairs, 4 pairs/thread -> 2^20 threads -> 4096 blocks of 256
    const unsigned threads = 256;
    const unsigned blocks  = (1u << 20) / threads;  // 4096

    hadamard_q5_kernel<<<blocks, threads>>>(in, out);
}